// round 13
// baseline (speedup 1.0000x reference)
#include <cuda_runtime.h>
#include <cuda_fp16.h>
#include <math.h>
#include <stdint.h>

// Problem constants (fixed by the reference setup_inputs()).
#define NN 8192
#define DD 512
#define INV_T 10.0f

// -------- scratch (allocation-free: __device__ globals) --------
__device__ __half g_fnh[(size_t)NN * DD];         // normalized features (fp16), 8 MB
__device__ float  g_S[(size_t)NN * NN];           // similarity logits, 256 MB
__device__ float  g_rowval[NN];
__device__ int    g_rowflag[NN];

// ================= helpers =================
__device__ __forceinline__ uint32_t smem_u32(const void* p) {
    return (uint32_t)__cvta_generic_to_shared(p);
}

#define CP_ASYNC16(dst, src) \
    asm volatile("cp.async.cg.shared.global [%0], [%1], 16;" :: "r"(dst), "l"(src) : "memory")
#define CP_COMMIT() asm volatile("cp.async.commit_group;" ::: "memory")
#define CP_WAIT1()  asm volatile("cp.async.wait_group 1;" ::: "memory")
#define CP_WAIT0()  asm volatile("cp.async.wait_group 0;" ::: "memory")

#define LDMATRIX_X4(r0, r1, r2, r3, addr) \
    asm volatile("ldmatrix.sync.aligned.m8n8.x4.shared.b16 {%0,%1,%2,%3}, [%4];" \
                 : "=r"(r0), "=r"(r1), "=r"(r2), "=r"(r3) : "r"(addr))

// m16n8k16 fp16 mma, fp32 accumulate
__device__ __forceinline__ void mma_f16(float* d, const uint32_t* a, uint32_t b0, uint32_t b1) {
    asm volatile(
        "mma.sync.aligned.m16n8k16.row.col.f32.f16.f16.f32 "
        "{%0,%1,%2,%3}, {%4,%5,%6,%7}, {%8,%9}, {%0,%1,%2,%3};"
        : "+f"(d[0]), "+f"(d[1]), "+f"(d[2]), "+f"(d[3])
        : "r"(a[0]), "r"(a[1]), "r"(a[2]), "r"(a[3]), "r"(b0), "r"(b1));
}

__device__ __forceinline__ float4 ldcs_f4(const float4* p) {
    float4 v;
    asm volatile("ld.global.cs.v4.f32 {%0,%1,%2,%3}, [%4];"
                 : "=f"(v.x), "=f"(v.y), "=f"(v.z), "=f"(v.w) : "l"(p));
    return v;
}

// ---------------------------------------------------------------
// Kernel 1: row-normalize -> fp16. One warp per row.
// ---------------------------------------------------------------
__global__ void normalize_kernel(const float* __restrict__ feats, int N) {
    int row  = blockIdx.x * (blockDim.x >> 5) + (threadIdx.x >> 5);
    int lane = threadIdx.x & 31;
    if (row >= N) return;
    const float2* src = (const float2*)(feats + (size_t)row * DD);
    float2 v[8];
    float ss = 0.f;
#pragma unroll
    for (int i = 0; i < 8; i++) {
        v[i] = src[lane + i * 32];
        ss += v[i].x * v[i].x + v[i].y * v[i].y;
    }
#pragma unroll
    for (int o = 16; o > 0; o >>= 1)
        ss += __shfl_xor_sync(0xffffffffu, ss, o);
    float inv = 1.0f / sqrtf(ss);
    __half2* dst = (__half2*)(g_fnh + (size_t)row * DD);
#pragma unroll
    for (int i = 0; i < 8; i++)
        dst[lane + i * 32] = __floats2half2_rn(v[i].x * inv, v[i].y * inv);
}

// ---------------------------------------------------------------
// Kernel 2: symmetric GEMM, block-upper-triangle tiles only.
// 256 threads (8 warps), BM=128, BN=256, warp tile 64x64 (2x4),
// 3-stage cp.async, direct + transposed (SMEM-staged) writes.
// ---------------------------------------------------------------
#define BMg 128
#define BNg 256
#define KC 32
#define NCHUNK (DD / KC)             // 16
#define RSH 40                        // half row stride (80 B)
#define A_BYTES (BMg * RSH * 2)       // 10240
#define B_BYTES (BNg * RSH * 2)       // 20480
#define STAGE_BYTES (A_BYTES + B_BYTES)   // 30720
#define NSTAGE 3
#define TSTRIDE 132                   // transpose staging stride (floats)
#define GEMM_SMEM (NSTAGE * STAGE_BYTES)  // 92160 (> 128*132*4, reused)
#define NTILES (32 * 33)              // 1056

extern __shared__ char smemc[];

__global__ __launch_bounds__(256, 1) void gemm_mma_kernel() {
    const int tid  = threadIdx.x;
    const int wid  = tid >> 5;
    const int lane = tid & 31;
    const int wm = wid & 1;           // warp row (x64)
    const int wn = wid >> 1;          // warp col (x64), 0..3
    const int g  = lane >> 2;         // group id 0..7
    const int t  = lane & 3;          // thread-in-group

    // decode linear block id -> (bx, by) with by in [0, 2bx+2)
    int id = blockIdx.x;
    int bx = (int)((sqrtf((float)(4 * id + 1)) - 1.f) * 0.5f);
    while ((bx + 1) * (bx + 2) <= id) bx++;
    while (bx * (bx + 1) > id) bx--;
    const int by = id - bx * (bx + 1);

    const uint32_t sbase = smem_u32(smemc);
    const __half* Ab = g_fnh + (size_t)by * BMg * DD;
    const __half* Bb = g_fnh + (size_t)bx * BNg * DD;

    // ldmatrix per-lane selectors (A: m16xk16 per x4; B: n16xk16 per x4)
    const int aRow  = (lane & 7) + ((lane >> 3) & 1) * 8;
    const int aC8   = (lane >> 4) & 1;
    const int bRow  = (lane & 7) + ((lane >> 4) & 1) * 8;
    const int bK8   = (lane >> 3) & 1;
    const uint32_t aoff = (uint32_t)(((wm * 64 + aRow) * RSH + aC8 * 8) * 2);
    const uint32_t boff = (uint32_t)(((wn * 64 + bRow) * RSH + bK8 * 8) * 2);

    float acc[4][8][4];
#pragma unroll
    for (int mt = 0; mt < 4; mt++)
#pragma unroll
        for (int nn = 0; nn < 8; nn++)
#pragma unroll
            for (int e = 0; e < 4; e++)
                acc[mt][nn][e] = 0.f;

#define LOAD_CHUNK(k) do {                                                     \
        int s_ = (k) % NSTAGE;                                                 \
        uint32_t sA_ = sbase + (uint32_t)(s_ * STAGE_BYTES);                   \
        uint32_t sB_ = sA_ + A_BYTES;                                          \
        int k0_ = (k) * KC;                                                    \
        _Pragma("unroll")                                                      \
        for (int i_ = 0; i_ < 2; i_++) {                                       \
            int idx_ = tid + i_ * 256;                                         \
            int r_ = idx_ >> 2, c_ = idx_ & 3;                                 \
            CP_ASYNC16(sA_ + (uint32_t)(r_ * 80 + c_ * 16),                    \
                       Ab + (size_t)r_ * DD + k0_ + c_ * 8);                   \
        }                                                                      \
        _Pragma("unroll")                                                      \
        for (int i_ = 0; i_ < 4; i_++) {                                       \
            int idx_ = tid + i_ * 256;                                         \
            int r_ = idx_ >> 2, c_ = idx_ & 3;                                 \
            CP_ASYNC16(sB_ + (uint32_t)(r_ * 80 + c_ * 16),                    \
                       Bb + (size_t)r_ * DD + k0_ + c_ * 8);                   \
        }                                                                      \
        CP_COMMIT();                                                           \
    } while (0)

    LOAD_CHUNK(0);
    LOAD_CHUNK(1);

    for (int k = 0; k < NCHUNK; k++) {
        if (k + 1 < NCHUNK) { CP_WAIT1(); } else { CP_WAIT0(); }
        __syncthreads();
        if (k + 2 < NCHUNK) LOAD_CHUNK(k + 2);   // stage (k+2)%3 == (k-1)%3, retired

        const int s = k % NSTAGE;
        const uint32_t sA = sbase + (uint32_t)(s * STAGE_BYTES) + aoff;
        const uint32_t sB = sbase + (uint32_t)(s * STAGE_BYTES) + A_BYTES + boff;

#pragma unroll
        for (int kk = 0; kk < 2; kk++) {
            uint32_t a[4][4];
#pragma unroll
            for (int mt = 0; mt < 4; mt++)
                LDMATRIX_X4(a[mt][0], a[mt][1], a[mt][2], a[mt][3],
                            sA + (uint32_t)(mt * 16 * 80 + kk * 32));
            uint32_t b[4][4];
#pragma unroll
            for (int np = 0; np < 4; np++)
                LDMATRIX_X4(b[np][0], b[np][1], b[np][2], b[np][3],
                            sB + (uint32_t)(np * 16 * 80 + kk * 32));
#pragma unroll
            for (int mt = 0; mt < 4; mt++) {
#pragma unroll
                for (int np = 0; np < 4; np++) {
                    mma_f16(acc[mt][np * 2 + 0], a[mt], b[np][0], b[np][1]);
                    mma_f16(acc[mt][np * 2 + 1], a[mt], b[np][2], b[np][3]);
                }
            }
        }
    }

    // --- pre-scale accumulators ---
#pragma unroll
    for (int mt = 0; mt < 4; mt++)
#pragma unroll
        for (int nn = 0; nn < 8; nn++)
#pragma unroll
            for (int e = 0; e < 4; e++)
                acc[mt][nn][e] *= INV_T;

    // --- direct write: tile (rows by*128.., cols bx*256..) ---
#pragma unroll
    for (int mt = 0; mt < 4; mt++) {
        int gi0 = by * BMg + wm * 64 + mt * 16 + g;
        float* r0 = g_S + (size_t)gi0 * NN + bx * BNg + wn * 64;
        float* r1 = r0 + (size_t)8 * NN;
#pragma unroll
        for (int nn = 0; nn < 8; nn++) {
            float2 w0, w1;
            w0.x = acc[mt][nn][0]; w0.y = acc[mt][nn][1];
            w1.x = acc[mt][nn][2]; w1.y = acc[mt][nn][3];
            *(float2*)(r0 + nn * 8 + 2 * t) = w0;
            *(float2*)(r1 + nn * 8 + 2 * t) = w1;
        }
    }

    // --- transposed write via SMEM staging (2 halves of 128 cols) ---
    float* smT = (float*)smemc;
    __syncthreads();   // pipeline stages dead; reuse smem
#pragma unroll
    for (int h = 0; h < 2; h++) {
        if ((wn >> 1) == h) {
            int cw = (wn & 1) * 64;
#pragma unroll
            for (int mt = 0; mt < 4; mt++) {
                int r = wm * 64 + mt * 16 + g;
#pragma unroll
                for (int nn = 0; nn < 8; nn++) {
                    int c = cw + nn * 8 + 2 * t;
                    smT[(size_t)c * TSTRIDE + r]           = acc[mt][nn][0];
                    smT[(size_t)(c + 1) * TSTRIDE + r]     = acc[mt][nn][1];
                    smT[(size_t)c * TSTRIDE + r + 8]       = acc[mt][nn][2];
                    smT[(size_t)(c + 1) * TSTRIDE + r + 8] = acc[mt][nn][3];
                }
            }
        }
        __syncthreads();
        const int colBase = bx * BNg + h * 128;
        const int rowBase = by * BMg;
#pragma unroll
        for (int it = 0; it < 16; it++) {
            int idx = tid + it * 256;       // 0..4095
            int c   = idx >> 5;             // 0..127
            int rq  = (idx & 31) * 4;
            float4 v = *(float4*)(smT + (size_t)c * TSTRIDE + rq);
            *(float4*)(g_S + (size_t)(colBase + c) * NN + rowBase + rq) = v;
        }
        __syncthreads();
    }
}

// ---------------------------------------------------------------
// Kernel 3: per-anchor epilogue. One block (512 thr) per row.
// ---------------------------------------------------------------
__global__ __launch_bounds__(512)
void row_loss_kernel(const int* __restrict__ labels,
                     const int* __restrict__ bad, int N) {
    __shared__ float srow[NN];       // 32 KB
    __shared__ int8_t slab[NN];      // 8 KB
    __shared__ float redm[512];
    __shared__ float reds[512];
    __shared__ int   redi[512];

    const int i = blockIdx.x;
    const int tid = threadIdx.x;
    const float* Srow = g_S + (size_t)i * N;

    for (int j = tid * 4; j < N; j += 512 * 4)
        *(float4*)(srow + j) = ldcs_f4((const float4*)(Srow + j));
    for (int j = tid; j < N; j += 512) {
        int lj = labels[j];
        slab[j] = (int8_t)((bad[j] == 0) ? lj : 3);
    }
    __syncthreads();

    const int8_t li = (int8_t)labels[i];
    const bool valid_i = (bad[i] == 0);

    // fused sweep: per-thread online LSE over negatives + pos count
    float m = -INFINITY, sum = 0.f;
    int pcnt = 0;
    for (int j = tid; j < N; j += 512) {
        int8_t lj = slab[j];
        if (lj != 3) {
            if (lj != li) {
                float v = srow[j];
                if (v > m) { sum = sum * expf(m - v) + 1.f; m = v; }
                else       { sum += expf(v - m); }
            } else if (j != i) pcnt++;
        }
    }
    redm[tid] = m; reds[tid] = sum; redi[tid] = pcnt;
    __syncthreads();
    for (int o = 256; o > 0; o >>= 1) {
        if (tid < o) {
            float m2 = redm[tid + o], s2 = reds[tid + o];
            float m1 = redm[tid],     s1 = reds[tid];
            if (m2 > m1) { float tm = m1; m1 = m2; m2 = tm;
                           float ts = s1; s1 = s2; s2 = ts; }
            if (m2 > -INFINITY) s1 += s2 * expf(m2 - m1);
            redm[tid] = m1; reds[tid] = s1;
            redi[tid] += redi[tid + o];
        }
        __syncthreads();
    }
    const float negmax = redm[0];
    const float negsum = reds[0];
    const int pos_cnt  = redi[0];
    const bool has_neg = (negmax > -INFINITY);
    const bool has_pos = (pos_cnt > 0);
    const bool processed = valid_i && has_neg;
    __syncthreads();

    if (!processed) {
        if (tid == 0) { g_rowval[i] = 0.f; g_rowflag[i] = 0; }
        return;
    }
    const float neg_lse = negmax + logf(negsum);

    float val;
    if (has_pos) {
        float ps = 0.f;
        for (int j = tid; j < N; j += 512) {
            int8_t lj = slab[j];
            if (lj == li && j != i) {
                float x = neg_lse - srow[j];
                ps += (x > 0.f) ? (x + log1pf(expf(-x))) : log1pf(expf(x));
            }
        }
        reds[tid] = ps;
        __syncthreads();
        for (int o = 256; o > 0; o >>= 1) {
            if (tid < o) reds[tid] += reds[tid + o];
            __syncthreads();
        }
        val = reds[0] / (float)pos_cnt;
    } else {
        float x = neg_lse - INV_T;
        val = (x > 0.f) ? (x + log1pf(expf(-x))) : log1pf(expf(x));
    }

    if (tid == 0) {
        g_rowval[i]  = val;
        g_rowflag[i] = has_pos ? 1 : 0;
    }
}

// ---------------------------------------------------------------
// Kernel 4: final reduction -> out[0] = total / (1 + count)
// ---------------------------------------------------------------
__global__ __launch_bounds__(1024)
void finalize_kernel(float* __restrict__ out, int N) {
    __shared__ float ssum[1024];
    __shared__ int   scnt[1024];
    int tid = threadIdx.x;
    float s = 0.f; int c = 0;
    for (int i = tid; i < N; i += 1024) {
        s += g_rowval[i];
        c += g_rowflag[i];
    }
    ssum[tid] = s; scnt[tid] = c;
    __syncthreads();
    for (int o = 512; o > 0; o >>= 1) {
        if (tid < o) { ssum[tid] += ssum[tid + o]; scnt[tid] += scnt[tid + o]; }
        __syncthreads();
    }
    if (tid == 0) out[0] = ssum[0] / (float)(1 + scnt[0]);
}

// ---------------------------------------------------------------
extern "C" void kernel_launch(void* const* d_in, const int* in_sizes, int n_in,
                              void* d_out, int out_size) {
    const float* feats  = (const float*)d_in[0];
    const int*   labels = (const int*)d_in[1];
    const int*   bad    = (const int*)d_in[2];
    float*       out    = (float*)d_out;

    const int N = in_sizes[1];   // 8192

    static int smem_set = 0;
    if (!smem_set) {
        cudaFuncSetAttribute(gemm_mma_kernel,
                             cudaFuncAttributeMaxDynamicSharedMemorySize, GEMM_SMEM);
        smem_set = 1;
    }

    normalize_kernel<<<N / 8, 256>>>(feats, N);
    gemm_mma_kernel<<<NTILES, 256, GEMM_SMEM>>>();
    row_loss_kernel<<<N, 512>>>(labels, bad, N);
    finalize_kernel<<<1, 1024>>>(out, N);
}